// round 1
// baseline (speedup 1.0000x reference)
#include <cuda_runtime.h>
#include <math.h>

#define BB 8192
#define KK 256
#define NN 128
#define MM 1024
#define TT 10

// ---- scratch (device globals; no allocation allowed) ----
__device__ float g_x[2 * KK * BB];     // x      [c][k][b]   16 MB
__device__ float g_t[2 * NN * BB];     // resid  [c][n][b]    8 MB
__device__ float g_xsp[MM * BB];       // xsp0   [m][b]      32 MB
__device__ float g_yt[2 * NN * BB];    // yt     [c][n][b]    8 MB
__device__ float g_acc[3];             // {sum|xsp0|, huber sum, count}

// ---------------------------------------------------------------------------
__global__ void k_init() {
    long idx = (long)blockIdx.x * blockDim.x + threadIdx.x;
    if (idx < 2L * KK * BB) g_x[idx] = 0.f;
    if (idx < 3) g_acc[idx] = 0.f;
}

// y (B, 2, N) -> g_yt (2, N, B).  Treat as transpose (B, 2N) -> (2N, B).
__global__ void k_transpose_y(const float* __restrict__ y) {
    __shared__ float tile[32][33];
    int b0 = blockIdx.x * 32;
    int j0 = blockIdx.y * 32;   // j = c*NN + n, 0..255
    int tx = threadIdx.x, ty = threadIdx.y;   // 32 x 8
#pragma unroll
    for (int r = 0; r < 32; r += 8)
        tile[ty + r][tx] = y[(long)(b0 + ty + r) * (2 * NN) + j0 + tx];
    __syncthreads();
#pragma unroll
    for (int r = 0; r < 32; r += 8)
        g_yt[(long)(j0 + ty + r) * BB + b0 + tx] = tile[tx][ty + r];
}

// block reduce over 256 threads; result valid on tid 0
__device__ __forceinline__ float block_reduce_256(float v, float* sbuf) {
    int tid = threadIdx.y * 16 + threadIdx.x;
#pragma unroll
    for (int o = 16; o > 0; o >>= 1) v += __shfl_down_sync(0xffffffffu, v, o);
    if ((tid & 31) == 0) sbuf[tid >> 5] = v;
    __syncthreads();
    if (tid < 8) {
        v = sbuf[tid];
#pragma unroll
        for (int o = 4; o > 0; o >>= 1) v += __shfl_down_sync(0xffu, v, o);
    }
    return v;
}

// ---------------------------------------------------------------------------
// grad1: t = W (x) - yt,   W (2,N,K), x (2,K,B) -> t (2,N,B)
__global__ void k_grad1(const float* __restrict__ W) {
    __shared__ __align__(16) float AsR[16][64], AsI[16][64], XsR[16][64], XsI[16][64];
    int b0 = blockIdx.x * 64, n0 = blockIdx.y * 64;
    int tx = threadIdx.x, ty = threadIdx.y;
    int tid = ty * 16 + tx;
    float accR[4][4] = {}, accI[4][4] = {};
    for (int kk = 0; kk < KK; kk += 16) {
        {   // A tile: W[c][n0+r][kk+jg..+3]
            int r = tid >> 2, jg = (tid & 3) * 4;
            float4 aR = *(const float4*)&W[(long)(n0 + r) * KK + kk + jg];
            float4 aI = *(const float4*)&W[(long)NN * KK + (long)(n0 + r) * KK + kk + jg];
            AsR[jg + 0][r] = aR.x; AsR[jg + 1][r] = aR.y; AsR[jg + 2][r] = aR.z; AsR[jg + 3][r] = aR.w;
            AsI[jg + 0][r] = aI.x; AsI[jg + 1][r] = aI.y; AsI[jg + 2][r] = aI.z; AsI[jg + 3][r] = aI.w;
        }
        {   // X tile from g_x
            int r = tid >> 4, cg = (tid & 15) * 4;
            *(float4*)&XsR[r][cg] = *(const float4*)&g_x[(long)(kk + r) * BB + b0 + cg];
            *(float4*)&XsI[r][cg] = *(const float4*)&g_x[(long)KK * BB + (long)(kk + r) * BB + b0 + cg];
        }
        __syncthreads();
#pragma unroll
        for (int j = 0; j < 16; j++) {
            float4 a4r = *(float4*)&AsR[j][ty * 4];
            float4 a4i = *(float4*)&AsI[j][ty * 4];
            float4 x4r = *(float4*)&XsR[j][tx * 4];
            float4 x4i = *(float4*)&XsI[j][tx * 4];
            float ar[4] = {a4r.x, a4r.y, a4r.z, a4r.w};
            float ai[4] = {a4i.x, a4i.y, a4i.z, a4i.w};
            float xr[4] = {x4r.x, x4r.y, x4r.z, x4r.w};
            float xi[4] = {x4i.x, x4i.y, x4i.z, x4i.w};
#pragma unroll
            for (int r = 0; r < 4; r++)
#pragma unroll
                for (int c = 0; c < 4; c++) {
                    accR[r][c] += ar[r] * xr[c] - ai[r] * xi[c];
                    accI[r][c] += ar[r] * xi[c] + ai[r] * xr[c];
                }
        }
        __syncthreads();
    }
#pragma unroll
    for (int r = 0; r < 4; r++)
#pragma unroll
        for (int c = 0; c < 4; c++) {
            long idx = (long)(n0 + ty * 4 + r) * BB + b0 + tx * 4 + c;
            g_t[idx] = accR[r][c] - g_yt[idx];
            g_t[(long)NN * BB + idx] = accI[r][c] - g_yt[(long)NN * BB + idx];
        }
}

// grad2: x -= gamma * (WX (t)),  WX (2,K,N), t (2,N,B)
__global__ void k_grad2(const float* __restrict__ WX, const float* __restrict__ gammas, int it) {
    __shared__ __align__(16) float AsR[16][64], AsI[16][64], XsR[16][64], XsI[16][64];
    int b0 = blockIdx.x * 64, k0 = blockIdx.y * 64;
    int tx = threadIdx.x, ty = threadIdx.y;
    int tid = ty * 16 + tx;
    float accR[4][4] = {}, accI[4][4] = {};
    for (int nn = 0; nn < NN; nn += 16) {
        {   // A tile: WX[c][k0+r][nn+jg..+3]  (row stride NN)
            int r = tid >> 2, jg = (tid & 3) * 4;
            float4 aR = *(const float4*)&WX[(long)(k0 + r) * NN + nn + jg];
            float4 aI = *(const float4*)&WX[(long)KK * NN + (long)(k0 + r) * NN + nn + jg];
            AsR[jg + 0][r] = aR.x; AsR[jg + 1][r] = aR.y; AsR[jg + 2][r] = aR.z; AsR[jg + 3][r] = aR.w;
            AsI[jg + 0][r] = aI.x; AsI[jg + 1][r] = aI.y; AsI[jg + 2][r] = aI.z; AsI[jg + 3][r] = aI.w;
        }
        {   // X tile from g_t
            int r = tid >> 4, cg = (tid & 15) * 4;
            *(float4*)&XsR[r][cg] = *(const float4*)&g_t[(long)(nn + r) * BB + b0 + cg];
            *(float4*)&XsI[r][cg] = *(const float4*)&g_t[(long)NN * BB + (long)(nn + r) * BB + b0 + cg];
        }
        __syncthreads();
#pragma unroll
        for (int j = 0; j < 16; j++) {
            float4 a4r = *(float4*)&AsR[j][ty * 4];
            float4 a4i = *(float4*)&AsI[j][ty * 4];
            float4 x4r = *(float4*)&XsR[j][tx * 4];
            float4 x4i = *(float4*)&XsI[j][tx * 4];
            float ar[4] = {a4r.x, a4r.y, a4r.z, a4r.w};
            float ai[4] = {a4i.x, a4i.y, a4i.z, a4i.w};
            float xr[4] = {x4r.x, x4r.y, x4r.z, x4r.w};
            float xi[4] = {x4i.x, x4i.y, x4i.z, x4i.w};
#pragma unroll
            for (int r = 0; r < 4; r++)
#pragma unroll
                for (int c = 0; c < 4; c++) {
                    accR[r][c] += ar[r] * xr[c] - ai[r] * xi[c];
                    accI[r][c] += ar[r] * xi[c] + ai[r] * xr[c];
                }
        }
        __syncthreads();
    }
    float gamma = gammas[it];
#pragma unroll
    for (int r = 0; r < 4; r++)
#pragma unroll
        for (int c = 0; c < 4; c++) {
            long idx = (long)(k0 + ty * 4 + r) * BB + b0 + tx * 4 + c;
            g_x[idx] -= gamma * accR[r][c];
            g_x[(long)KK * BB + idx] -= gamma * accI[r][c];
        }
}

// encode: xsp0 = shrink(E0re x_re - E0im x_im, eta) ; accumulate sum|.| and (last iter) count
__global__ void k_encode(const float* __restrict__ E0, const float* __restrict__ etas,
                         int it, int is_last) {
    __shared__ __align__(16) float AsR[16][64], AsI[16][64], XsR[16][64], XsI[16][64];
    __shared__ float red[8];
    int b0 = blockIdx.x * 64, m0 = blockIdx.y * 64;
    int tx = threadIdx.x, ty = threadIdx.y;
    int tid = ty * 16 + tx;
    float acc[4][4] = {};
    for (int kk = 0; kk < KK; kk += 16) {
        {
            int r = tid >> 2, jg = (tid & 3) * 4;
            float4 aR = *(const float4*)&E0[(long)(m0 + r) * KK + kk + jg];
            float4 aI = *(const float4*)&E0[(long)MM * KK + (long)(m0 + r) * KK + kk + jg];
            AsR[jg + 0][r] = aR.x; AsR[jg + 1][r] = aR.y; AsR[jg + 2][r] = aR.z; AsR[jg + 3][r] = aR.w;
            AsI[jg + 0][r] = aI.x; AsI[jg + 1][r] = aI.y; AsI[jg + 2][r] = aI.z; AsI[jg + 3][r] = aI.w;
        }
        {
            int r = tid >> 4, cg = (tid & 15) * 4;
            *(float4*)&XsR[r][cg] = *(const float4*)&g_x[(long)(kk + r) * BB + b0 + cg];
            *(float4*)&XsI[r][cg] = *(const float4*)&g_x[(long)KK * BB + (long)(kk + r) * BB + b0 + cg];
        }
        __syncthreads();
#pragma unroll
        for (int j = 0; j < 16; j++) {
            float4 a4r = *(float4*)&AsR[j][ty * 4];
            float4 a4i = *(float4*)&AsI[j][ty * 4];
            float4 x4r = *(float4*)&XsR[j][tx * 4];
            float4 x4i = *(float4*)&XsI[j][tx * 4];
            float ar[4] = {a4r.x, a4r.y, a4r.z, a4r.w};
            float ai[4] = {a4i.x, a4i.y, a4i.z, a4i.w};
            float xr[4] = {x4r.x, x4r.y, x4r.z, x4r.w};
            float xi[4] = {x4i.x, x4i.y, x4i.z, x4i.w};
#pragma unroll
            for (int r = 0; r < 4; r++)
#pragma unroll
                for (int c = 0; c < 4; c++)
                    acc[r][c] += ar[r] * xr[c] - ai[r] * xi[c];
        }
        __syncthreads();
    }
    float eta = etas[it];
    float lsum = 0.f, csum = 0.f;
#pragma unroll
    for (int r = 0; r < 4; r++)
#pragma unroll
        for (int c = 0; c < 4; c++) {
            float z = acc[r][c];
            float a = fabsf(z) - eta;
            float v = (a > 0.f) ? copysignf(a, z) : 0.f;
            g_xsp[(long)(m0 + ty * 4 + r) * BB + b0 + tx * 4 + c] = v;
            lsum += fabsf(v);
            if (is_last) csum += (fabsf(v) > 1e-3f) ? 1.f : 0.f;
        }
    float s = block_reduce_256(lsum, red);
    if (tid == 0) atomicAdd(&g_acc[0], s);
    if (is_last) {
        __syncthreads();
        float cs = block_reduce_256(csum, red);
        if (tid == 0) atomicAdd(&g_acc[2], cs);
    }
}

// decode: x_map_re = E0re^T xsp0 ; x_map_im = -E0im^T xsp0 ; huber(x_old, x_map) ; x <- x_map
__global__ void k_decode(const float* __restrict__ E0) {
    __shared__ __align__(16) float AsR[16][64], AsI[16][64], Xs[16][64];
    __shared__ float red[8];
    int b0 = blockIdx.x * 64, k0 = blockIdx.y * 64;
    int tx = threadIdx.x, ty = threadIdx.y;
    int tid = ty * 16 + tx;
    float accR[4][4] = {}, accI[4][4] = {};
    for (int mm = 0; mm < MM; mm += 16) {
        {   // A tile: As[j][r] = E0[c][mm+j][k0+rg..] (contiguous in k)
            int j = tid >> 4, rg = (tid & 15) * 4;
            *(float4*)&AsR[j][rg] = *(const float4*)&E0[(long)(mm + j) * KK + k0 + rg];
            *(float4*)&AsI[j][rg] = *(const float4*)&E0[(long)MM * KK + (long)(mm + j) * KK + k0 + rg];
            *(float4*)&Xs[j][rg]  = *(const float4*)&g_xsp[(long)(mm + j) * BB + b0 + rg];
        }
        __syncthreads();
#pragma unroll
        for (int j = 0; j < 16; j++) {
            float4 a4r = *(float4*)&AsR[j][ty * 4];
            float4 a4i = *(float4*)&AsI[j][ty * 4];
            float4 x4  = *(float4*)&Xs[j][tx * 4];
            float ar[4] = {a4r.x, a4r.y, a4r.z, a4r.w};
            float ai[4] = {a4i.x, a4i.y, a4i.z, a4i.w};
            float xv[4] = {x4.x, x4.y, x4.z, x4.w};
#pragma unroll
            for (int r = 0; r < 4; r++)
#pragma unroll
                for (int c = 0; c < 4; c++) {
                    accR[r][c] += ar[r] * xv[c];
                    accI[r][c] += ai[r] * xv[c];
                }
        }
        __syncthreads();
    }
    float hsum = 0.f;
#pragma unroll
    for (int r = 0; r < 4; r++)
#pragma unroll
        for (int c = 0; c < 4; c++) {
            long idx = (long)(k0 + ty * 4 + r) * BB + b0 + tx * 4 + c;
            float xmR = accR[r][c];
            float xmI = -accI[r][c];
            float oR = g_x[idx];
            float oI = g_x[(long)KK * BB + idx];
            float d = oR - xmR; float ad = fabsf(d);
            hsum += (ad < 1.f) ? 0.5f * d * d : ad - 0.5f;
            d = oI - xmI; ad = fabsf(d);
            hsum += (ad < 1.f) ? 0.5f * d * d : ad - 0.5f;
            g_x[idx] = xmR;
            g_x[(long)KK * BB + idx] = xmI;
        }
    float s = block_reduce_256(hsum, red);
    if (tid == 0) atomicAdd(&g_acc[1], s);
}

// out[c][b][k] = g_x[c][k][b]
__global__ void k_output(float* __restrict__ out) {
    __shared__ float tile[32][33];
    int c = blockIdx.z;
    int b0 = blockIdx.x * 32, k0 = blockIdx.y * 32;
    int tx = threadIdx.x, ty = threadIdx.y;   // 32 x 8
#pragma unroll
    for (int r = 0; r < 32; r += 8)
        tile[ty + r][tx] = g_x[(long)c * KK * BB + (long)(k0 + ty + r) * BB + b0 + tx];
    __syncthreads();
#pragma unroll
    for (int r = 0; r < 32; r += 8)
        out[(long)c * BB * KK + (long)(b0 + ty + r) * KK + k0 + tx] = tile[tx][ty + r];
}

__global__ void k_scalars(float* __restrict__ out) {
    if (threadIdx.x == 0 && blockIdx.x == 0) {
        long base = 2L * BB * KK;
        out[base + 0] = g_acc[0] / (float)BB;
        out[base + 1] = g_acc[1] / ((float)2 * KK * BB * TT);
        out[base + 2] = g_acc[2] / (float)BB;
    }
}

// ---------------------------------------------------------------------------
extern "C" void kernel_launch(void* const* d_in, const int* in_sizes, int n_in,
                              void* d_out, int out_size) {
    const float* y      = (const float*)d_in[0];
    const float* W      = (const float*)d_in[1];
    const float* WX     = (const float*)d_in[2];
    const float* E0     = (const float*)d_in[3];
    const float* etas   = (const float*)d_in[4];
    const float* gammas = (const float*)d_in[5];
    float* out = (float*)d_out;

    k_init<<<(2 * KK * BB + 255) / 256, 256>>>();
    k_transpose_y<<<dim3(BB / 32, (2 * NN) / 32), dim3(32, 8)>>>(y);
    for (int i = 1; i <= TT; i++) {
        k_grad1<<<dim3(BB / 64, NN / 64), dim3(16, 16)>>>(W);
        k_grad2<<<dim3(BB / 64, KK / 64), dim3(16, 16)>>>(WX, gammas, i);
        k_encode<<<dim3(BB / 64, MM / 64), dim3(16, 16)>>>(E0, etas, i, (i == TT) ? 1 : 0);
        k_decode<<<dim3(BB / 64, KK / 64), dim3(16, 16)>>>(E0);
    }
    k_output<<<dim3(BB / 32, KK / 32, 2), dim3(32, 8)>>>(out);
    k_scalars<<<1, 32>>>(out);
}

// round 3
// speedup vs baseline: 1.6597x; 1.6597x over previous
#include <cuda_runtime.h>
#include <cstdint>
#include <math.h>

#define BB 8192
#define KD 256     // complex dim K
#define MD 1024    // sparse dim M
#define TT 10

#define LDA 36               // padded smem row stride (floats)
#define TSZ (128 * LDA)      // one tile (floats)
#define SMEM_FLOATS (4 * TSZ)   // A/X x 2 stages
#define SMEM_BYTES (SMEM_FLOATS * 4)   // 73728

// ---------------- scratch ----------------
__device__ float g_x[BB * 512];          // x    [b][2K]
__device__ float g_xmap[BB * 512];       // xmap [b][2K]
__device__ float g_b0[BB * 512];         // b0   [b][2K]
__device__ float g_xsp[(size_t)BB * MD]; // xsp  [b][M]
__device__ float g_R[512 * 512];
__device__ float g_WXr[512 * 256];
__device__ float g_E[MD * 512];
__device__ float g_D[512 * MD];
__device__ float g_acc[3];

// ---------------- mma helpers ----------------
__device__ __forceinline__ void mma8(float* c, uint32_t a0, uint32_t a1, uint32_t a2, uint32_t a3,
                                     uint32_t b0, uint32_t b1) {
    asm volatile(
        "mma.sync.aligned.m16n8k8.row.col.f32.tf32.tf32.f32 "
        "{%0,%1,%2,%3}, {%4,%5,%6,%7}, {%8,%9}, {%0,%1,%2,%3};"
        : "+f"(c[0]), "+f"(c[1]), "+f"(c[2]), "+f"(c[3])
        : "r"(a0), "r"(a1), "r"(a2), "r"(a3), "r"(b0), "r"(b1));
}
__device__ __forceinline__ void split1(float v, uint32_t& h, uint32_t& l) {
    uint32_t hb;
    asm("cvt.rna.tf32.f32 %0, %1;" : "=r"(hb) : "f"(v));
    float lo = v - __uint_as_float(hb);
    uint32_t lb;
    asm("cvt.rna.tf32.f32 %0, %1;" : "=r"(lb) : "f"(lo));
    h = hb; l = lb;
}

// ---------------- tensor-core GEMM: D[m][b] = A[m][:] . X[b][:] ----------------
// EPI: 0 = plain store, 1 = x-update, 2 = shrink(+L1,+count), 3 = xmap(+huber)
template <int KIN, int MOUT, int EPI>
__global__ void __launch_bounds__(256, 1) k_gemm(
    const float* __restrict__ A, const float* __restrict__ Xm, float* __restrict__ OUT,
    const float* __restrict__ aux1, const float* __restrict__ aux2,
    const float* __restrict__ scal, int last)
{
    extern __shared__ float sm[];
    float* As = sm;             // [2][128][LDA]
    float* Xs = sm + 2 * TSZ;   // [2][128][LDA]

    const int tid = threadIdx.x;
    const int wid = tid >> 5, lane = tid & 31;
    const int g = lane >> 2, tg = lane & 3;
    const int b0 = blockIdx.x * 128;
    const int m0 = blockIdx.y * 128;
    const int m_off = (wid & 1) * 64;
    const int n_off = (wid >> 1) * 32;

    constexpr int NS = KIN / 32;

    float c[4][4][4];
#pragma unroll
    for (int i = 0; i < 4; i++)
#pragma unroll
        for (int j = 0; j < 4; j++)
#pragma unroll
            for (int q = 0; q < 4; q++) c[i][j][q] = 0.f;

    // stage 0 -> smem buf 0
    {
        const int row = tid >> 3, cg = (tid & 7) * 4;
#pragma unroll
        for (int r = 0; r < 4; r++) {
            int rr = row + 32 * r;
            float4 v = *(const float4*)(A + (size_t)(m0 + rr) * KIN + cg);
            *(float4*)(As + rr * LDA + cg) = v;
            float4 w = *(const float4*)(Xm + (size_t)(b0 + rr) * KIN + cg);
            *(float4*)(Xs + rr * LDA + cg) = w;
        }
    }
    __syncthreads();

    for (int kt = 0; kt < NS; kt++) {
        const int buf = kt & 1;
        float4 av[4], xv[4];
        if (kt + 1 < NS) {
            const int kk = (kt + 1) * 32;
            const int row = tid >> 3, cg = (tid & 7) * 4;
#pragma unroll
            for (int r = 0; r < 4; r++) {
                int rr = row + 32 * r;
                av[r] = *(const float4*)(A + (size_t)(m0 + rr) * KIN + kk + cg);
                xv[r] = *(const float4*)(Xm + (size_t)(b0 + rr) * KIN + kk + cg);
            }
        }

        const float* Ab = As + buf * TSZ;
        const float* Xb = Xs + buf * TSZ;
#pragma unroll
        for (int ks = 0; ks < 4; ks++) {
            const float* ap = Ab + (m_off + g) * LDA + ks * 8 + tg;
            const float* xp = Xb + (n_off + g) * LDA + ks * 8 + tg;
            uint32_t ah[4][4], al[4][4], xh[4][2], xl[4][2];
#pragma unroll
            for (int mf = 0; mf < 4; mf++) {
                split1(ap[mf * 16 * LDA],            ah[mf][0], al[mf][0]);
                split1(ap[mf * 16 * LDA + 8 * LDA],  ah[mf][1], al[mf][1]);
                split1(ap[mf * 16 * LDA + 4],        ah[mf][2], al[mf][2]);
                split1(ap[mf * 16 * LDA + 8 * LDA + 4], ah[mf][3], al[mf][3]);
            }
#pragma unroll
            for (int nf = 0; nf < 4; nf++) {
                split1(xp[nf * 8 * LDA],     xh[nf][0], xl[nf][0]);
                split1(xp[nf * 8 * LDA + 4], xh[nf][1], xl[nf][1]);
            }
#pragma unroll
            for (int mf = 0; mf < 4; mf++)
#pragma unroll
                for (int nf = 0; nf < 4; nf++) {
                    mma8(c[mf][nf], ah[mf][0], ah[mf][1], ah[mf][2], ah[mf][3], xh[nf][0], xh[nf][1]);
                    mma8(c[mf][nf], ah[mf][0], ah[mf][1], ah[mf][2], ah[mf][3], xl[nf][0], xl[nf][1]);
                    mma8(c[mf][nf], al[mf][0], al[mf][1], al[mf][2], al[mf][3], xh[nf][0], xh[nf][1]);
                }
        }
        __syncthreads();
        if (kt + 1 < NS) {
            const int row = tid >> 3, cg = (tid & 7) * 4;
            float* Ao = As + (buf ^ 1) * TSZ;
            float* Xo = Xs + (buf ^ 1) * TSZ;
#pragma unroll
            for (int r = 0; r < 4; r++) {
                int rr = row + 32 * r;
                *(float4*)(Ao + rr * LDA + cg) = av[r];
                *(float4*)(Xo + rr * LDA + cg) = xv[r];
            }
            __syncthreads();
        }
    }

    // ---------------- epilogue ----------------
    float s_a = 0.f, s_b = 0.f;
    float gam = 0.f, eta = 0.f;
    if (EPI == 1) gam = scal[0];
    if (EPI == 2) eta = scal[0];
#pragma unroll
    for (int mf = 0; mf < 4; mf++)
#pragma unroll
        for (int nf = 0; nf < 4; nf++) {
#pragma unroll
            for (int q = 0; q < 4; q++) {
                int m = m0 + m_off + mf * 16 + g + (q >= 2 ? 8 : 0);
                int b = b0 + n_off + nf * 8 + tg * 2 + (q & 1);
                size_t o = (size_t)b * MOUT + m;
                float d = c[mf][nf][q];
                if (EPI == 0) {
                    OUT[o] = d;
                } else if (EPI == 1) {
                    OUT[o] = aux1[o] - gam * (d - aux2[o]);
                } else if (EPI == 2) {
                    float ad = fabsf(d) - eta;
                    float v = (ad > 0.f) ? copysignf(ad, d) : 0.f;
                    OUT[o] = v;
                    s_a += fabsf(v);
                    if (last) s_b += (fabsf(v) > 1e-3f) ? 1.f : 0.f;
                } else {
                    float xo = aux1[o];
                    float dd = xo - d; float ad = fabsf(dd);
                    s_a += (ad < 1.f) ? 0.5f * dd * dd : ad - 0.5f;
                    OUT[o] = d;
                }
            }
        }
    if (EPI == 2 || EPI == 3) {
#pragma unroll
        for (int off = 16; off > 0; off >>= 1) {
            s_a += __shfl_down_sync(0xffffffffu, s_a, off);
            if (EPI == 2) s_b += __shfl_down_sync(0xffffffffu, s_b, off);
        }
        if (lane == 0) {
            atomicAdd(&g_acc[EPI == 2 ? 0 : 1], s_a);
            if (EPI == 2 && last) atomicAdd(&g_acc[2], s_b);
        }
    }
}

// ---------------- prep kernels ----------------
__global__ void k_zero() { if (threadIdx.x < 3) g_acc[threadIdx.x] = 0.f; }

// R = real form of P = WX(2,256,128) @ W(2,128,256)
__global__ void k_prep_R(const float* __restrict__ W, const float* __restrict__ WX) {
    int j = blockIdx.x * 16 + threadIdx.x;   // 0..255
    int i = blockIdx.y * 16 + threadIdx.y;   // 0..255
    float pre = 0.f, pim = 0.f;
#pragma unroll 4
    for (int n = 0; n < 128; n++) {
        float ar = WX[i * 128 + n], ai = WX[32768 + i * 128 + n];
        float br = W[n * 256 + j],  bi = W[32768 + n * 256 + j];
        pre += ar * br - ai * bi;
        pim += ar * bi + ai * br;
    }
    g_R[i * 512 + j] = pre;
    g_R[i * 512 + j + 256] = -pim;
    g_R[(i + 256) * 512 + j] = pim;
    g_R[(i + 256) * 512 + j + 256] = pre;
}

__global__ void k_prep_WXr(const float* __restrict__ WX) {
    int idx = blockIdx.x * 256 + threadIdx.x;          // 512*256
    int np = idx & 255, j = idx >> 8;
    int jj = j & 255, jr = j >> 8;
    int nn = np & 127, nc = np >> 7;
    float re = WX[jj * 128 + nn], im = WX[32768 + jj * 128 + nn];
    float v;
    if (jr == 0) v = (nc == 0) ? re : -im;
    else         v = (nc == 0) ? im :  re;
    g_WXr[idx] = v;
}

__global__ void k_prep_E(const float* __restrict__ E0) {
    int idx = blockIdx.x * 256 + threadIdx.x;          // 1024*512
    int k = idx & 511, mrow = idx >> 9;
    g_E[idx] = (k < 256) ? E0[mrow * 256 + k] : -E0[262144 + mrow * 256 + (k - 256)];
}

__global__ void k_prep_D(const float* __restrict__ E0) {
    int idx = blockIdx.x * 256 + threadIdx.x;          // 512*1024
    int mrow = idx & 1023, j = idx >> 10;
    g_D[idx] = (j < 256) ? E0[mrow * 256 + j] : -E0[262144 + mrow * 256 + (j - 256)];
}

__global__ void k_x1(const float* __restrict__ gammas) {
    int idx = blockIdx.x * 256 + threadIdx.x;          // 8192*512
    g_x[idx] = gammas[1] * g_b0[idx];
}

__global__ void k_final(float* __restrict__ out) {
    int idx = blockIdx.x * 256 + threadIdx.x;          // 2*8192*256
    int k = idx & 255, b = (idx >> 8) & 8191, cch = idx >> 21;
    out[idx] = g_xmap[(size_t)b * 512 + cch * 256 + k];
}

__global__ void k_scalars(float* __restrict__ out) {
    if (threadIdx.x == 0 && blockIdx.x == 0) {
        size_t base = 2ull * BB * KD;
        out[base + 0] = g_acc[0] / (float)BB;
        out[base + 1] = g_acc[1] / ((float)2 * KD * BB * TT);
        out[base + 2] = g_acc[2] / (float)BB;
    }
}

// ---------------- launch ----------------
extern "C" void kernel_launch(void* const* d_in, const int* in_sizes, int n_in,
                              void* d_out, int out_size) {
    const float* y      = (const float*)d_in[0];
    const float* W      = (const float*)d_in[1];
    const float* WX     = (const float*)d_in[2];
    const float* E0     = (const float*)d_in[3];
    const float* etas   = (const float*)d_in[4];
    const float* gammas = (const float*)d_in[5];
    float* out = (float*)d_out;

    void *pR, *pWXr, *pE, *pD, *pX, *pXmap, *pB0, *pXsp;
    cudaGetSymbolAddress(&pR, g_R);
    cudaGetSymbolAddress(&pWXr, g_WXr);
    cudaGetSymbolAddress(&pE, g_E);
    cudaGetSymbolAddress(&pD, g_D);
    cudaGetSymbolAddress(&pX, g_x);
    cudaGetSymbolAddress(&pXmap, g_xmap);
    cudaGetSymbolAddress(&pB0, g_b0);
    cudaGetSymbolAddress(&pXsp, g_xsp);
    const float *fR = (const float*)pR, *fWXr = (const float*)pWXr;
    const float *fE = (const float*)pE, *fD = (const float*)pD;
    float *fX = (float*)pX, *fXmap = (float*)pXmap, *fB0 = (float*)pB0, *fXsp = (float*)pXsp;

    cudaFuncSetAttribute(k_gemm<256, 512, 0>, cudaFuncAttributeMaxDynamicSharedMemorySize, SMEM_BYTES);
    cudaFuncSetAttribute(k_gemm<512, 512, 1>, cudaFuncAttributeMaxDynamicSharedMemorySize, SMEM_BYTES);
    cudaFuncSetAttribute(k_gemm<512, 1024, 2>, cudaFuncAttributeMaxDynamicSharedMemorySize, SMEM_BYTES);
    cudaFuncSetAttribute(k_gemm<1024, 512, 3>, cudaFuncAttributeMaxDynamicSharedMemorySize, SMEM_BYTES);

    k_zero<<<1, 32>>>();
    k_prep_R<<<dim3(16, 16), dim3(16, 16)>>>(W, WX);
    k_prep_WXr<<<512 * 256 / 256, 256>>>(WX);
    k_prep_E<<<1024 * 512 / 256, 256>>>(E0);
    k_prep_D<<<512 * 1024 / 256, 256>>>(E0);

    // b0 = WXr . y  -> g_b0 [b][512]   (y is [b][2N] = [b][256] row-major, matches X layout)
    k_gemm<256, 512, 0><<<dim3(BB / 128, 4), 256, SMEM_BYTES>>>(fWXr, y, fB0,
        nullptr, nullptr, nullptr, 0);
    k_x1<<<BB * 512 / 256, 256>>>(gammas);

    for (int i = 1; i <= TT; i++) {
        if (i > 1)
            k_gemm<512, 512, 1><<<dim3(BB / 128, 4), 256, SMEM_BYTES>>>(fR, fXmap, fX,
                fXmap, fB0, gammas + i, 0);
        k_gemm<512, 1024, 2><<<dim3(BB / 128, 8), 256, SMEM_BYTES>>>(fE, fX, fXsp,
            nullptr, nullptr, etas + i, (i == TT) ? 1 : 0);
        k_gemm<1024, 512, 3><<<dim3(BB / 128, 4), 256, SMEM_BYTES>>>(fD, fXsp, fXmap,
            fX, nullptr, nullptr, 0);
    }
    k_final<<<2 * BB * KD / 256, 256>>>(out);
    k_scalars<<<1, 32>>>(out);
}

// round 4
// speedup vs baseline: 1.7263x; 1.0401x over previous
#include <cuda_runtime.h>
#include <cstdint>
#include <math.h>

#define BB 8192
#define KD 256     // complex dim K
#define MD 1024    // sparse dim M
#define TT 10

#define LDA 36               // padded smem row stride (floats)
#define TSZ (128 * LDA)      // one tile (floats)
#define SMEM_FLOATS (4 * TSZ)          // A/X x 2 stages
#define SMEM_BYTES (SMEM_FLOATS * 4)   // 73728

// ---------------- scratch ----------------
__device__ float g_x[BB * 512];          // x    [b][2K]
__device__ float g_xmap[BB * 512];       // xmap [b][2K]
__device__ float g_b0[BB * 512];         // b0   [b][2K]
__device__ float g_xsp[(size_t)BB * MD]; // xsp  [b][M]
__device__ float g_R[512 * 512];
__device__ float g_WXr[512 * 256];
__device__ float g_E[MD * 512];
__device__ float g_D[512 * MD];
__device__ float g_acc[3];

// ---------------- asm helpers ----------------
__device__ __forceinline__ uint32_t smem_u32(const void* p) {
    uint32_t a;
    asm("{ .reg .u64 t; cvta.to.shared.u64 t, %1; cvt.u32.u64 %0, t; }" : "=r"(a) : "l"(p));
    return a;
}
__device__ __forceinline__ void cp16(uint32_t dst, const void* src) {
    asm volatile("cp.async.cg.shared.global [%0], [%1], 16;" :: "r"(dst), "l"(src));
}
__device__ __forceinline__ void cp_commit() {
    asm volatile("cp.async.commit_group;" ::: "memory");
}
template <int N>
__device__ __forceinline__ void cp_wait() {
    asm volatile("cp.async.wait_group %0;" :: "n"(N) : "memory");
}
__device__ __forceinline__ void mma8(float* c, uint32_t a0, uint32_t a1, uint32_t a2, uint32_t a3,
                                     uint32_t b0, uint32_t b1) {
    asm volatile(
        "mma.sync.aligned.m16n8k8.row.col.f32.tf32.tf32.f32 "
        "{%0,%1,%2,%3}, {%4,%5,%6,%7}, {%8,%9}, {%0,%1,%2,%3};"
        : "+f"(c[0]), "+f"(c[1]), "+f"(c[2]), "+f"(c[3])
        : "r"(a0), "r"(a1), "r"(a2), "r"(a3), "r"(b0), "r"(b1));
}
__device__ __forceinline__ void split1(float v, uint32_t& h, uint32_t& l) {
    uint32_t hb;
    asm("cvt.rna.tf32.f32 %0, %1;" : "=r"(hb) : "f"(v));
    float lo = v - __uint_as_float(hb);
    uint32_t lb;
    asm("cvt.rna.tf32.f32 %0, %1;" : "=r"(lb) : "f"(lo));
    h = hb; l = lb;
}

// ---------------- tensor-core GEMM: D[m][b] = A[m][:] . X[b][:] ----------------
// EPI: 0 = plain store, 1 = x-update, 2 = shrink(+L1,+count), 3 = xmap(+huber)
template <int KIN, int MOUT, int EPI>
__global__ void __launch_bounds__(256, 2) k_gemm(
    const float* __restrict__ A, const float* __restrict__ Xm, float* __restrict__ OUT,
    const float* __restrict__ aux1, const float* __restrict__ aux2,
    const float* __restrict__ scal, int last)
{
    extern __shared__ float sm[];
    float* As = sm;             // [2][128][LDA]
    float* Xs = sm + 2 * TSZ;   // [2][128][LDA]

    const int tid = threadIdx.x;
    const int wid = tid >> 5, lane = tid & 31;
    const int g = lane >> 2, tg = lane & 3;
    const int b0 = blockIdx.x * 128;
    const int m0 = blockIdx.y * 128;
    const int m_off = (wid & 1) * 64;
    const int n_off = (wid >> 1) * 32;

    constexpr int NS = KIN / 32;

    const int crow = tid >> 3, ccg = (tid & 7) * 4;   // copy indexing

    // issue stage st -> buf st&1
    auto issue = [&](int st) {
        const int kk = st * 32;
        float* Ao = As + (st & 1) * TSZ;
        float* Xo = Xs + (st & 1) * TSZ;
#pragma unroll
        for (int r = 0; r < 4; r++) {
            int rr = crow + 32 * r;
            cp16(smem_u32(Ao + rr * LDA + ccg), A + (size_t)(m0 + rr) * KIN + kk + ccg);
            cp16(smem_u32(Xo + rr * LDA + ccg), Xm + (size_t)(b0 + rr) * KIN + kk + ccg);
        }
        cp_commit();
    };

    float c[4][4][4];
#pragma unroll
    for (int i = 0; i < 4; i++)
#pragma unroll
        for (int j = 0; j < 4; j++)
#pragma unroll
            for (int q = 0; q < 4; q++) c[i][j][q] = 0.f;

    issue(0);
    issue(1);

    for (int kt = 0; kt < NS; kt++) {
        cp_wait<1>();
        __syncthreads();

        const int buf = kt & 1;
        const float* Ab = As + buf * TSZ;
        const float* Xb = Xs + buf * TSZ;
#pragma unroll
        for (int ks = 0; ks < 4; ks++) {
            const float* ap = Ab + (m_off + g) * LDA + ks * 8 + tg;
            const float* xp = Xb + (n_off + g) * LDA + ks * 8 + tg;
            uint32_t ah[4][4], al[4][4], xh[4][2], xl[4][2];
#pragma unroll
            for (int mf = 0; mf < 4; mf++) {
                split1(ap[mf * 16 * LDA],               ah[mf][0], al[mf][0]);
                split1(ap[mf * 16 * LDA + 8 * LDA],     ah[mf][1], al[mf][1]);
                split1(ap[mf * 16 * LDA + 4],           ah[mf][2], al[mf][2]);
                split1(ap[mf * 16 * LDA + 8 * LDA + 4], ah[mf][3], al[mf][3]);
            }
#pragma unroll
            for (int nf = 0; nf < 4; nf++) {
                split1(xp[nf * 8 * LDA],     xh[nf][0], xl[nf][0]);
                split1(xp[nf * 8 * LDA + 4], xh[nf][1], xl[nf][1]);
            }
#pragma unroll
            for (int mf = 0; mf < 4; mf++)
#pragma unroll
                for (int nf = 0; nf < 4; nf++) {
                    mma8(c[mf][nf], ah[mf][0], ah[mf][1], ah[mf][2], ah[mf][3], xh[nf][0], xh[nf][1]);
                    mma8(c[mf][nf], ah[mf][0], ah[mf][1], ah[mf][2], ah[mf][3], xl[nf][0], xl[nf][1]);
                    mma8(c[mf][nf], al[mf][0], al[mf][1], al[mf][2], al[mf][3], xh[nf][0], xh[nf][1]);
                }
        }
        __syncthreads();
        if (kt + 2 < NS) issue(kt + 2);
        else cp_commit();           // keep group count aligned for cp_wait<1>
    }

    // ---------------- epilogue ----------------
    float s_a = 0.f, s_b = 0.f;
    float gam = 0.f, eta = 0.f;
    if (EPI == 1) gam = scal[0];
    if (EPI == 2) eta = scal[0];
#pragma unroll
    for (int mf = 0; mf < 4; mf++)
#pragma unroll
        for (int nf = 0; nf < 4; nf++) {
#pragma unroll
            for (int q = 0; q < 4; q++) {
                int m = m0 + m_off + mf * 16 + g + (q >= 2 ? 8 : 0);
                int b = b0 + n_off + nf * 8 + tg * 2 + (q & 1);
                size_t o = (size_t)b * MOUT + m;
                float d = c[mf][nf][q];
                if (EPI == 0) {
                    OUT[o] = d;
                } else if (EPI == 1) {
                    OUT[o] = aux1[o] - gam * (d - aux2[o]);
                } else if (EPI == 2) {
                    float ad = fabsf(d) - eta;
                    float v = (ad > 0.f) ? copysignf(ad, d) : 0.f;
                    OUT[o] = v;
                    s_a += fabsf(v);
                    if (last) s_b += (fabsf(v) > 1e-3f) ? 1.f : 0.f;
                } else {
                    float xo = aux1[o];
                    float dd = xo - d; float ad = fabsf(dd);
                    s_a += (ad < 1.f) ? 0.5f * dd * dd : ad - 0.5f;
                    OUT[o] = d;
                }
            }
        }
    if (EPI == 2 || EPI == 3) {
#pragma unroll
        for (int off = 16; off > 0; off >>= 1) {
            s_a += __shfl_down_sync(0xffffffffu, s_a, off);
            if (EPI == 2) s_b += __shfl_down_sync(0xffffffffu, s_b, off);
        }
        if (lane == 0) {
            atomicAdd(&g_acc[EPI == 2 ? 0 : 1], s_a);
            if (EPI == 2 && last) atomicAdd(&g_acc[2], s_b);
        }
    }
}

// ---------------- prep kernels ----------------
__global__ void k_zero() { if (threadIdx.x < 3) g_acc[threadIdx.x] = 0.f; }

// R = real form of P = WX(2,256,128) @ W(2,128,256)
__global__ void k_prep_R(const float* __restrict__ W, const float* __restrict__ WX) {
    int j = blockIdx.x * 16 + threadIdx.x;   // 0..255
    int i = blockIdx.y * 16 + threadIdx.y;   // 0..255
    float pre = 0.f, pim = 0.f;
#pragma unroll 4
    for (int n = 0; n < 128; n++) {
        float ar = WX[i * 128 + n], ai = WX[32768 + i * 128 + n];
        float br = W[n * 256 + j],  bi = W[32768 + n * 256 + j];
        pre += ar * br - ai * bi;
        pim += ar * bi + ai * br;
    }
    g_R[i * 512 + j] = pre;
    g_R[i * 512 + j + 256] = -pim;
    g_R[(i + 256) * 512 + j] = pim;
    g_R[(i + 256) * 512 + j + 256] = pre;
}

__global__ void k_prep_WXr(const float* __restrict__ WX) {
    int idx = blockIdx.x * 256 + threadIdx.x;          // 512*256
    int np = idx & 255, j = idx >> 8;
    int jj = j & 255, jr = j >> 8;
    int nn = np & 127, nc = np >> 7;
    float re = WX[jj * 128 + nn], im = WX[32768 + jj * 128 + nn];
    float v;
    if (jr == 0) v = (nc == 0) ? re : -im;
    else         v = (nc == 0) ? im :  re;
    g_WXr[idx] = v;
}

__global__ void k_prep_E(const float* __restrict__ E0) {
    int idx = blockIdx.x * 256 + threadIdx.x;          // 1024*512
    int k = idx & 511, mrow = idx >> 9;
    g_E[idx] = (k < 256) ? E0[mrow * 256 + k] : -E0[262144 + mrow * 256 + (k - 256)];
}

__global__ void k_prep_D(const float* __restrict__ E0) {
    int idx = blockIdx.x * 256 + threadIdx.x;          // 512*1024
    int mrow = idx & 1023, j = idx >> 10;
    g_D[idx] = (j < 256) ? E0[mrow * 256 + j] : -E0[262144 + mrow * 256 + (j - 256)];
}

__global__ void k_x1(const float* __restrict__ gammas) {
    int idx = blockIdx.x * 256 + threadIdx.x;          // 8192*512
    g_x[idx] = gammas[1] * g_b0[idx];
}

__global__ void k_final(float* __restrict__ out) {
    int idx = blockIdx.x * 256 + threadIdx.x;          // 2*8192*256
    int k = idx & 255, b = (idx >> 8) & 8191, cch = idx >> 21;
    out[idx] = g_xmap[(size_t)b * 512 + cch * 256 + k];
}

__global__ void k_scalars(float* __restrict__ out) {
    if (threadIdx.x == 0 && blockIdx.x == 0) {
        size_t base = 2ull * BB * KD;
        out[base + 0] = g_acc[0] / (float)BB;
        out[base + 1] = g_acc[1] / ((float)2 * KD * BB * TT);
        out[base + 2] = g_acc[2] / (float)BB;
    }
}

// ---------------- launch ----------------
extern "C" void kernel_launch(void* const* d_in, const int* in_sizes, int n_in,
                              void* d_out, int out_size) {
    const float* y      = (const float*)d_in[0];
    const float* W      = (const float*)d_in[1];
    const float* WX     = (const float*)d_in[2];
    const float* E0     = (const float*)d_in[3];
    const float* etas   = (const float*)d_in[4];
    const float* gammas = (const float*)d_in[5];
    float* out = (float*)d_out;

    void *pR, *pWXr, *pE, *pD, *pX, *pXmap, *pB0, *pXsp;
    cudaGetSymbolAddress(&pR, g_R);
    cudaGetSymbolAddress(&pWXr, g_WXr);
    cudaGetSymbolAddress(&pE, g_E);
    cudaGetSymbolAddress(&pD, g_D);
    cudaGetSymbolAddress(&pX, g_x);
    cudaGetSymbolAddress(&pXmap, g_xmap);
    cudaGetSymbolAddress(&pB0, g_b0);
    cudaGetSymbolAddress(&pXsp, g_xsp);
    const float *fR = (const float*)pR, *fWXr = (const float*)pWXr;
    const float *fE = (const float*)pE, *fD = (const float*)pD;
    float *fX = (float*)pX, *fXmap = (float*)pXmap, *fB0 = (float*)pB0, *fXsp = (float*)pXsp;

    cudaFuncSetAttribute(k_gemm<256, 512, 0>, cudaFuncAttributeMaxDynamicSharedMemorySize, SMEM_BYTES);
    cudaFuncSetAttribute(k_gemm<512, 512, 1>, cudaFuncAttributeMaxDynamicSharedMemorySize, SMEM_BYTES);
    cudaFuncSetAttribute(k_gemm<512, 1024, 2>, cudaFuncAttributeMaxDynamicSharedMemorySize, SMEM_BYTES);
    cudaFuncSetAttribute(k_gemm<1024, 512, 3>, cudaFuncAttributeMaxDynamicSharedMemorySize, SMEM_BYTES);

    k_zero<<<1, 32>>>();
    k_prep_R<<<dim3(16, 16), dim3(16, 16)>>>(W, WX);
    k_prep_WXr<<<512 * 256 / 256, 256>>>(WX);
    k_prep_E<<<1024 * 512 / 256, 256>>>(E0);
    k_prep_D<<<512 * 1024 / 256, 256>>>(E0);

    // b0 = WXr . y  -> g_b0 [b][512]   (y is [b][2N] = [b][256] row-major, matches X layout)
    k_gemm<256, 512, 0><<<dim3(BB / 128, 4), 256, SMEM_BYTES>>>(fWXr, y, fB0,
        nullptr, nullptr, nullptr, 0);
    k_x1<<<BB * 512 / 256, 256>>>(gammas);

    for (int i = 1; i <= TT; i++) {
        if (i > 1)
            k_gemm<512, 512, 1><<<dim3(BB / 128, 4), 256, SMEM_BYTES>>>(fR, fXmap, fX,
                fXmap, fB0, gammas + i, 0);
        k_gemm<512, 1024, 2><<<dim3(BB / 128, 8), 256, SMEM_BYTES>>>(fE, fX, fXsp,
            nullptr, nullptr, etas + i, (i == TT) ? 1 : 0);
        k_gemm<1024, 512, 3><<<dim3(BB / 128, 4), 256, SMEM_BYTES>>>(fD, fXsp, fXmap,
            fX, nullptr, nullptr, 0);
    }
    k_final<<<2 * BB * KD / 256, 256>>>(out);
    k_scalars<<<1, 32>>>(out);
}